// round 7
// baseline (speedup 1.0000x reference)
#include <cuda_runtime.h>
#include <math_constants.h>

// Fixed shapes
#define B      32
#define C0     512
#define C1     1024
#define HW0    1444      // 38*38, divisible by 4
#define HW4_0  361       // HW0/4 in float4 units
#define HW1    361       // 19*19
#define THRESH 0.15f
#define NCH0   8         // channel chunks, level 0 (CPC = 64)
#define NCH1   16        // channel chunks, level 1 (CPC = 64)
#define CPC0   (C0/NCH0) // 64
#define CPC1   (C1/NCH1) // 64

// Output layout (float32): fw[2], embT0, embT1, embS0, embS1
#define OFF_FW  0
#define OFF_ET0 2
#define OFF_ET1 (OFF_ET0 + B*HW0)
#define OFF_ES0 (OFF_ET1 + B*HW1)
#define OFF_ES1 (OFF_ES0 + B*HW0)

// Static device scratch
__device__ float d_w0[B * C0];
__device__ float d_w1[B * C1];
__device__ float d_pc0[NCH0 * B * HW0];
__device__ float d_pt0[NCH0 * B * HW0];
__device__ float d_ps0[NCH0 * B * HW0];
__device__ float d_pc1[NCH1 * B * HW1];
__device__ float d_pt1[NCH1 * B * HW1];
__device__ float d_ps1[NCH1 * B * HW1];
__device__ float d_score[2 * B];
__device__ int   d_fcnt[2 * B];   // per-(level,b) arrival counters
__device__ int   d_gcnt = 0;      // global finisher counter (fw)

// ---------------------------------------------------------------------------
// Stage 1: GradCAM weights.
// Level 0 (blocks [0,1024)): one warp = 2 rows, float4.
// Level 1 (blocks [1024,2048)): one warp = 4 consecutive rows read as ONE
// contiguous float4 stream (4*361 floats = 361 f4, 16B-aligned). Only f4
// indices 90/180/270 straddle row boundaries.
// ---------------------------------------------------------------------------
__global__ __launch_bounds__(256)
void k_gmean_all(const float* __restrict__ g0, const float* __restrict__ g1,
                 float* __restrict__ w0, float* __restrict__ w1) {
    const int lane = threadIdx.x & 31;
    const int warp = threadIdx.x >> 5;

    if (blockIdx.x < 1024) {
        // level 0: 8192 row-pairs
        const int pair = blockIdx.x * 8 + warp;
        const float4* p0 = reinterpret_cast<const float4*>(g0) + (size_t)(2 * pair) * HW4_0;
        const float4* p1 = p0 + HW4_0;
        float4 a0 = {0,0,0,0}, a1 = {0,0,0,0};
        #pragma unroll 2
        for (int i = lane; i < HW4_0; i += 32) {
            float4 v0 = __ldcs(p0 + i);
            float4 v1 = __ldcs(p1 + i);
            a0.x += v0.x; a0.y += v0.y; a0.z += v0.z; a0.w += v0.w;
            a1.x += v1.x; a1.y += v1.y; a1.z += v1.z; a1.w += v1.w;
        }
        float s0 = (a0.x + a0.y) + (a0.z + a0.w);
        float s1 = (a1.x + a1.y) + (a1.z + a1.w);
        #pragma unroll
        for (int o = 16; o; o >>= 1) {
            s0 += __shfl_xor_sync(0xffffffffu, s0, o);
            s1 += __shfl_xor_sync(0xffffffffu, s1, o);
        }
        if (lane == 0) {
            w0[2 * pair]     = s0 * (1.f / HW0);
            w0[2 * pair + 1] = s1 * (1.f / HW0);
        }
    } else {
        // level 1: 8192 row-quads, float4 over the contiguous 4-row span
        const int quad = (blockIdx.x - 1024) * 8 + warp;
        const float4* p4 = reinterpret_cast<const float4*>(g1 + (size_t)(4 * quad) * HW1);
        float s0 = 0.f, s1 = 0.f, s2 = 0.f, s3 = 0.f;
        #pragma unroll 4
        for (int i = lane; i < 361; i += 32) {
            float4 v = __ldcs(p4 + i);
            if (i == 90) {                 // elems 360..363: row0 | row1
                s0 += v.x; s1 += (v.y + v.z) + v.w;
            } else if (i == 180) {         // elems 720..723: row1 | row2
                s1 += v.x + v.y; s2 += v.z + v.w;
            } else if (i == 270) {         // elems 1080..1083: row2 | row3
                s2 += (v.x + v.y) + v.z; s3 += v.w;
            } else {
                const float sum = (v.x + v.y) + (v.z + v.w);
                const int e = 4 * i;
                if      (e < 361)  s0 += sum;
                else if (e < 722)  s1 += sum;
                else if (e < 1083) s2 += sum;
                else               s3 += sum;
            }
        }
        #pragma unroll
        for (int o = 16; o; o >>= 1) {
            s0 += __shfl_xor_sync(0xffffffffu, s0, o);
            s1 += __shfl_xor_sync(0xffffffffu, s1, o);
            s2 += __shfl_xor_sync(0xffffffffu, s2, o);
            s3 += __shfl_xor_sync(0xffffffffu, s3, o);
        }
        if (lane == 0) {
            const float inv = 1.f / HW1;
            w1[4 * quad]     = s0 * inv;
            w1[4 * quad + 1] = s1 * inv;
            w1[4 * quad + 2] = s2 * inv;
            w1[4 * quad + 3] = s3 * inv;
        }
    }
}

// ---------------------------------------------------------------------------
// Inline finish (runs inside the last-arriving cam block of each (level,b)).
// Two passes over L2-resident partials: (A) stats, (B) mask + write.
// 128 threads, fixed-order sums -> deterministic.
// ---------------------------------------------------------------------------
template <int C, int HW, int CHUNKS>
__device__ void finish_b(const float* __restrict__ pc, const float* __restrict__ pt,
                         const float* __restrict__ ps,
                         float* __restrict__ outT, float* __restrict__ outS,
                         float* __restrict__ score_slot, int b,
                         float* rmx, float* rsm) {
    const int t = threadIdx.x;
    float mx = -CUDART_INF_F, sm = 0.f;
    for (int i = t; i < HW; i += 128) {
        float cc = 0.f;
        #pragma unroll
        for (int ch = 0; ch < CHUNKS; ++ch)
            cc += pc[(size_t)(ch * B + b) * HW + i];
        mx = fmaxf(mx, cc);
        sm += fmaxf(cc, 0.f);
    }
    rmx[t] = mx; rsm[t] = sm;
    __syncthreads();
    #pragma unroll
    for (int s = 64; s; s >>= 1) {
        if (t < s) { rmx[t] = fmaxf(rmx[t], rmx[t + s]); rsm[t] += rsm[t + s]; }
        __syncthreads();
    }
    if (t == 0) *score_slot = rsm[0] * (1.f / (float)HW);
    const float thr = fabsf(rmx[0] * THRESH);

    constexpr float invC = 1.f / (float)C;
    for (int i = t; i < HW; i += 128) {
        float cc = 0.f, tt = 0.f, ss = 0.f;
        #pragma unroll
        for (int ch = 0; ch < CHUNKS; ++ch) {
            const size_t o = (size_t)(ch * B + b) * HW + i;
            cc += pc[o]; tt += pt[o]; ss += ps[o];
        }
        const bool m = cc > thr;
        const size_t o = (size_t)b * HW + i;
        outT[o] = m ? tt * invC : 0.f;
        outS[o] = m ? ss * invC : 0.f;
    }
}

// ---------------------------------------------------------------------------
// Stage 2 (fused): partial cam / sumT / sumS + inline per-(level,b) finish
// + fw by the globally-last finisher. grid = (3, B, NCH0+NCH1), block 128.
// ---------------------------------------------------------------------------
__global__ __launch_bounds__(128)
void k_camfin(const float* __restrict__ Tf0, const float* __restrict__ Sf0,
              const float* __restrict__ w0,
              float* __restrict__ pc0, float* __restrict__ pt0, float* __restrict__ ps0,
              const float* __restrict__ Tf1, const float* __restrict__ Sf1,
              const float* __restrict__ w1,
              float* __restrict__ pc1, float* __restrict__ pt1, float* __restrict__ ps1,
              float* __restrict__ out, float* __restrict__ score) {
    __shared__ float sw[64];
    __shared__ float rmx[128], rsm[128];
    __shared__ int   sflag;

    const int b   = blockIdx.y;
    const int z   = blockIdx.z;
    const int tid = threadIdx.x;
    const int level = (z < NCH0) ? 0 : 1;

    // ----------------- cam partial work -----------------
    if (level == 0) {
        const int chunk = z;
        if (tid < CPC0) sw[tid] = w0[b * C0 + chunk * CPC0 + tid];
        __syncthreads();

        const int q = blockIdx.x * 128 + tid;   // float4 index within row
        if (q < HW4_0) {
            const size_t rb = (size_t)(b * C0 + chunk * CPC0) * HW4_0 + q;
            const float4* tp = reinterpret_cast<const float4*>(Tf0) + rb;
            const float4* sp = reinterpret_cast<const float4*>(Sf0) + rb;
            float4 ac = {0,0,0,0}, at = {0,0,0,0}, as4 = {0,0,0,0};
            #pragma unroll 8
            for (int c = 0; c < CPC0; ++c) {
                float4 t = __ldcs(tp + (size_t)c * HW4_0);
                float4 s = __ldcs(sp + (size_t)c * HW4_0);
                const float wv = sw[c];
                ac.x = fmaf(wv, t.x, ac.x); ac.y = fmaf(wv, t.y, ac.y);
                ac.z = fmaf(wv, t.z, ac.z); ac.w = fmaf(wv, t.w, ac.w);
                at.x += t.x; at.y += t.y; at.z += t.z; at.w += t.w;
                as4.x += s.x; as4.y += s.y; as4.z += s.z; as4.w += s.w;
            }
            const size_t o = (size_t)(chunk * B + b) * HW4_0 + q;
            reinterpret_cast<float4*>(pc0)[o] = ac;
            reinterpret_cast<float4*>(pt0)[o] = at;
            reinterpret_cast<float4*>(ps0)[o] = as4;
        }
    } else {
        const int chunk = z - NCH0;
        if (tid < CPC1) sw[tid] = w1[b * C1 + chunk * CPC1 + tid];
        __syncthreads();

        const int hw = blockIdx.x * 128 + tid;
        if (hw < HW1) {
            const size_t rb = (size_t)(b * C1 + chunk * CPC1) * HW1 + hw;
            const float* tp = Tf1 + rb;
            const float* sp = Sf1 + rb;
            float ac = 0.f, at = 0.f, as_ = 0.f;
            #pragma unroll 8
            for (int c = 0; c < CPC1; ++c) {
                float t = __ldcs(tp + (size_t)c * HW1);
                float s = __ldcs(sp + (size_t)c * HW1);
                ac = fmaf(sw[c], t, ac);
                at += t;
                as_ += s;
            }
            const size_t o = (size_t)(chunk * B + b) * HW1 + hw;
            pc1[o] = ac; pt1[o] = at; ps1[o] = as_;
        }
    }

    // ----------------- arrival; last block for (level,b) finishes -----------------
    __syncthreads();
    if (tid == 0) {
        __threadfence();
        const int target = (level == 0) ? 3 * NCH0 : 3 * NCH1;  // 24 / 48
        int* cnt = &d_fcnt[level * B + b];
        const int old = atomicAdd(cnt, 1);
        sflag = (old == target - 1);
        if (sflag) *cnt = 0;   // reset for graph replay
    }
    __syncthreads();
    if (!sflag) return;
    __threadfence();   // acquire: see all producers' partials

    if (level == 0) {
        finish_b<C0, HW0, NCH0>(pc0, pt0, ps0,
                                out + OFF_ET0, out + OFF_ES0,
                                score + b, b, rmx, rsm);
    } else {
        finish_b<C1, HW1, NCH1>(pc1, pt1, ps1,
                                out + OFF_ET1, out + OFF_ES1,
                                score + B + b, b, rmx, rsm);
    }

    // ----------------- globally-last finisher computes fw -----------------
    __syncthreads();
    if (tid == 0) {
        __threadfence();
        const int old = atomicAdd(&d_gcnt, 1);
        sflag = (old == 2 * B - 1);
        if (sflag) d_gcnt = 0;
    }
    __syncthreads();
    if (sflag && tid == 0) {
        __threadfence();
        float s0 = 0.f, s1 = 0.f;
        for (int i = 0; i < B; ++i) { s0 += score[i]; s1 += score[B + i]; }
        const float inv = 1.f / (s0 + s1);
        out[OFF_FW + 0] = s0 * inv;
        out[OFF_FW + 1] = s1 * inv;
    }
}

// ---------------------------------------------------------------------------
extern "C" void kernel_launch(void* const* d_in, const int* in_sizes, int n_in,
                              void* d_out, int out_size) {
    const float* Tf0 = (const float*)d_in[0];
    const float* Tf1 = (const float*)d_in[1];
    const float* Sf0 = (const float*)d_in[2];
    const float* Sf1 = (const float*)d_in[3];
    const float* g0  = (const float*)d_in[4];
    const float* g1  = (const float*)d_in[5];
    float* out = (float*)d_out;

    float *w0, *w1, *pc0, *pt0, *ps0, *pc1, *pt1, *ps1, *score;
    cudaGetSymbolAddress((void**)&w0,  d_w0);
    cudaGetSymbolAddress((void**)&w1,  d_w1);
    cudaGetSymbolAddress((void**)&pc0, d_pc0);
    cudaGetSymbolAddress((void**)&pt0, d_pt0);
    cudaGetSymbolAddress((void**)&ps0, d_ps0);
    cudaGetSymbolAddress((void**)&pc1, d_pc1);
    cudaGetSymbolAddress((void**)&pt1, d_pt1);
    cudaGetSymbolAddress((void**)&ps1, d_ps1);
    cudaGetSymbolAddress((void**)&score, d_score);

    // Stage 1: GradCAM weights (level-1 now float4 via contiguous quads)
    k_gmean_all<<<2048, 256>>>(g0, g1, w0, w1);

    // Stage 2: cam partials + inline finish + fw, single launch
    {
        dim3 grid(3, B, NCH0 + NCH1);   // 3 x 32 x 24 = 2304 blocks of 128
        k_camfin<<<grid, 128>>>(Tf0, Sf0, w0, pc0, pt0, ps0,
                                Tf1, Sf1, w1, pc1, pt1, ps1,
                                out, score);
    }
}

// round 8
// speedup vs baseline: 1.0554x; 1.0554x over previous
#include <cuda_runtime.h>
#include <math_constants.h>

// Fixed shapes
#define B      32
#define C0     512
#define C1     1024
#define HW0    1444      // 38*38, divisible by 4
#define HW4_0  361       // HW0/4 in float4 units
#define HW1    361       // 19*19
#define THRESH 0.15f
#define NCH0   8         // channel chunks, level 0 (CPC = 64)
#define NCH1   16        // channel chunks, level 1 (CPC = 64)
#define CPC0   (C0/NCH0) // 64
#define CPC1   (C1/NCH1) // 64

// Output layout (float32): fw[2], embT0, embT1, embS0, embS1
#define OFF_FW  0
#define OFF_ET0 2
#define OFF_ET1 (OFF_ET0 + B*HW0)
#define OFF_ES0 (OFF_ET1 + B*HW1)
#define OFF_ES1 (OFF_ES0 + B*HW0)

// Static device scratch
__device__ float d_w0[B * C0];
__device__ float d_w1[B * C1];
__device__ float d_pc0[NCH0 * B * HW0];
__device__ float d_pt0[NCH0 * B * HW0];
__device__ float d_ps0[NCH0 * B * HW0];
__device__ float d_pc1[NCH1 * B * HW1];
__device__ float d_pt1[NCH1 * B * HW1];
__device__ float d_ps1[NCH1 * B * HW1];
__device__ float d_score[2 * B];
__device__ int   d_cnt = 0;

// ---------------------------------------------------------------------------
// Stage 1: GradCAM weights, all-float4.
// Level 0 (blocks [0,1024)): one warp = 2 rows, float4.
// Level 1 (blocks [1024,2048)): one warp = 4 consecutive rows read as ONE
// contiguous float4 stream (4*361 floats = 361 f4, base 16B-aligned). Only
// f4 indices 90/180/270 straddle row boundaries.
// ---------------------------------------------------------------------------
__global__ __launch_bounds__(256)
void k_gmean_all(const float* __restrict__ g0, const float* __restrict__ g1,
                 float* __restrict__ w0, float* __restrict__ w1) {
    const int lane = threadIdx.x & 31;
    const int warp = threadIdx.x >> 5;

    if (blockIdx.x < 1024) {
        // level 0: 8192 row-pairs
        const int pair = blockIdx.x * 8 + warp;
        const float4* p0 = reinterpret_cast<const float4*>(g0) + (size_t)(2 * pair) * HW4_0;
        const float4* p1 = p0 + HW4_0;
        float4 a0 = {0,0,0,0}, a1 = {0,0,0,0};
        #pragma unroll 2
        for (int i = lane; i < HW4_0; i += 32) {
            float4 v0 = __ldcs(p0 + i);
            float4 v1 = __ldcs(p1 + i);
            a0.x += v0.x; a0.y += v0.y; a0.z += v0.z; a0.w += v0.w;
            a1.x += v1.x; a1.y += v1.y; a1.z += v1.z; a1.w += v1.w;
        }
        float s0 = (a0.x + a0.y) + (a0.z + a0.w);
        float s1 = (a1.x + a1.y) + (a1.z + a1.w);
        #pragma unroll
        for (int o = 16; o; o >>= 1) {
            s0 += __shfl_xor_sync(0xffffffffu, s0, o);
            s1 += __shfl_xor_sync(0xffffffffu, s1, o);
        }
        if (lane == 0) {
            w0[2 * pair]     = s0 * (1.f / HW0);
            w0[2 * pair + 1] = s1 * (1.f / HW0);
        }
    } else {
        // level 1: 8192 row-quads, float4 over the contiguous 4-row span
        const int quad = (blockIdx.x - 1024) * 8 + warp;
        const float4* p4 = reinterpret_cast<const float4*>(g1 + (size_t)(4 * quad) * HW1);
        float s0 = 0.f, s1 = 0.f, s2 = 0.f, s3 = 0.f;
        #pragma unroll 4
        for (int i = lane; i < 361; i += 32) {
            float4 v = __ldcs(p4 + i);
            if (i == 90) {                 // elems 360..363: row0 | row1
                s0 += v.x; s1 += (v.y + v.z) + v.w;
            } else if (i == 180) {         // elems 720..723: row1 | row2
                s1 += v.x + v.y; s2 += v.z + v.w;
            } else if (i == 270) {         // elems 1080..1083: row2 | row3
                s2 += (v.x + v.y) + v.z; s3 += v.w;
            } else {
                const float sum = (v.x + v.y) + (v.z + v.w);
                const int e = 4 * i;
                if      (e < 361)  s0 += sum;
                else if (e < 722)  s1 += sum;
                else if (e < 1083) s2 += sum;
                else               s3 += sum;
            }
        }
        #pragma unroll
        for (int o = 16; o; o >>= 1) {
            s0 += __shfl_xor_sync(0xffffffffu, s0, o);
            s1 += __shfl_xor_sync(0xffffffffu, s1, o);
            s2 += __shfl_xor_sync(0xffffffffu, s2, o);
            s3 += __shfl_xor_sync(0xffffffffu, s3, o);
        }
        if (lane == 0) {
            const float inv = 1.f / HW1;
            w1[4 * quad]     = s0 * inv;
            w1[4 * quad + 1] = s1 * inv;
            w1[4 * quad + 2] = s2 * inv;
            w1[4 * quad + 3] = s3 * inv;
        }
    }
}

// ---------------------------------------------------------------------------
// Stage 2 (R5/R6 proven version): per channel-chunk partial cam/sumT/sumS.
// 128-thread blocks, each thread owns the full 64-channel loop.
// grid = (3, B, NCH0+NCH1) = 2304 blocks -> single wave, regs ~32.
// ---------------------------------------------------------------------------
__global__ __launch_bounds__(128)
void k_cam_all(const float* __restrict__ Tf0, const float* __restrict__ Sf0,
               const float* __restrict__ w0,
               float* __restrict__ pc0, float* __restrict__ pt0, float* __restrict__ ps0,
               const float* __restrict__ Tf1, const float* __restrict__ Sf1,
               const float* __restrict__ w1,
               float* __restrict__ pc1, float* __restrict__ pt1, float* __restrict__ ps1) {
    __shared__ float sw[64];

    const int b   = blockIdx.y;
    const int z   = blockIdx.z;
    const int tid = threadIdx.x;

    if (z < NCH0) {
        // ----- level 0: float4 along hw -----
        const int chunk = z;
        if (tid < CPC0) sw[tid] = w0[b * C0 + chunk * CPC0 + tid];
        __syncthreads();

        const int q = blockIdx.x * 128 + tid;   // float4 index within row
        if (q >= HW4_0) return;
        const size_t rb = (size_t)(b * C0 + chunk * CPC0) * HW4_0 + q;
        const float4* tp = reinterpret_cast<const float4*>(Tf0) + rb;
        const float4* sp = reinterpret_cast<const float4*>(Sf0) + rb;

        float4 ac = {0,0,0,0}, at = {0,0,0,0}, as4 = {0,0,0,0};
        #pragma unroll 8
        for (int c = 0; c < CPC0; ++c) {
            float4 t = __ldcs(tp + (size_t)c * HW4_0);
            float4 s = __ldcs(sp + (size_t)c * HW4_0);
            float  wv = sw[c];
            ac.x = fmaf(wv, t.x, ac.x); ac.y = fmaf(wv, t.y, ac.y);
            ac.z = fmaf(wv, t.z, ac.z); ac.w = fmaf(wv, t.w, ac.w);
            at.x += t.x; at.y += t.y; at.z += t.z; at.w += t.w;
            as4.x += s.x; as4.y += s.y; as4.z += s.z; as4.w += s.w;
        }
        const size_t o = (size_t)(chunk * B + b) * HW4_0 + q;
        reinterpret_cast<float4*>(pc0)[o] = ac;
        reinterpret_cast<float4*>(pt0)[o] = at;
        reinterpret_cast<float4*>(ps0)[o] = as4;
    } else {
        // ----- level 1: scalar along hw -----
        const int chunk = z - NCH0;
        if (tid < CPC1) sw[tid] = w1[b * C1 + chunk * CPC1 + tid];
        __syncthreads();

        const int hw = blockIdx.x * 128 + tid;
        if (hw >= HW1) return;
        const size_t rb = (size_t)(b * C1 + chunk * CPC1) * HW1 + hw;
        const float* tp = Tf1 + rb;
        const float* sp = Sf1 + rb;

        float ac = 0.f, at = 0.f, as_ = 0.f;
        #pragma unroll 8
        for (int c = 0; c < CPC1; ++c) {
            float t = __ldcs(tp + (size_t)c * HW1);
            float s = __ldcs(sp + (size_t)c * HW1);
            ac = fmaf(sw[c], t, ac);
            at += t;
            as_ += s;
        }
        const size_t o = (size_t)(chunk * B + b) * HW1 + hw;
        pc1[o] = ac; pt1[o] = at; ps1[o] = as_;
    }
}

// ---------------------------------------------------------------------------
// Stage 3 (R6 proven version): combine chunks + stats + mask + fw.
// grid = 64 blocks (32 per level), 512 threads.
// ---------------------------------------------------------------------------
template <int C, int HW, int CHUNKS, int PPT>
__device__ __forceinline__
void finish_impl(const float* __restrict__ pc, const float* __restrict__ pt,
                 const float* __restrict__ ps,
                 float* __restrict__ outT, float* __restrict__ outS,
                 float* __restrict__ score_slot, int b,
                 float* smx, float* ssm, float* sthr) {
    constexpr float invC  = 1.f / (float)C;
    constexpr float invHW = 1.f / (float)HW;
    const int t = threadIdx.x;

    float camv[PPT], tv[PPT], sv[PPT];
    float mx = -CUDART_INF_F, sm = 0.f;

    #pragma unroll
    for (int p = 0; p < PPT; ++p) {
        const int i = p * 512 + t;
        camv[p] = 0.f; tv[p] = 0.f; sv[p] = 0.f;
        if (i < HW) {
            float cc = 0.f, tt = 0.f, ss = 0.f;
            #pragma unroll
            for (int ch = 0; ch < CHUNKS; ++ch) {
                const size_t o = (size_t)(ch * B + b) * HW + i;
                cc += pc[o]; tt += pt[o]; ss += ps[o];
            }
            camv[p] = cc;
            tv[p]   = tt * invC;
            sv[p]   = ss * invC;
            mx = fmaxf(mx, cc);
            sm += fmaxf(cc, 0.f);
        }
    }

    smx[t] = mx; ssm[t] = sm;
    __syncthreads();
    #pragma unroll
    for (int s = 256; s; s >>= 1) {
        if (t < s) { smx[t] = fmaxf(smx[t], smx[t + s]); ssm[t] += ssm[t + s]; }
        __syncthreads();
    }
    if (t == 0) {
        *score_slot = ssm[0] * invHW;
        *sthr = fabsf(smx[0] * THRESH);
    }
    __syncthreads();
    const float thr = *sthr;

    #pragma unroll
    for (int p = 0; p < PPT; ++p) {
        const int i = p * 512 + t;
        if (i < HW) {
            const bool m = camv[p] > thr;
            const size_t o = (size_t)b * HW + i;
            outT[o] = m ? tv[p] : 0.f;
            outS[o] = m ? sv[p] : 0.f;
        }
    }
}

__global__ __launch_bounds__(512)
void k_finish_all(const float* __restrict__ pc0, const float* __restrict__ pt0,
                  const float* __restrict__ ps0,
                  const float* __restrict__ pc1, const float* __restrict__ pt1,
                  const float* __restrict__ ps1,
                  float* __restrict__ out, float* __restrict__ score) {
    __shared__ float smx[512], ssm[512], sthr;

    if (blockIdx.x < 32) {
        const int b = blockIdx.x;
        finish_impl<C0, HW0, NCH0, 3>(pc0, pt0, ps0,
                                      out + OFF_ET0, out + OFF_ES0,
                                      score + b, b, smx, ssm, &sthr);
    } else {
        const int b = blockIdx.x - 32;
        finish_impl<C1, HW1, NCH1, 1>(pc1, pt1, ps1,
                                      out + OFF_ET1, out + OFF_ES1,
                                      score + B + b, b, smx, ssm, &sthr);
    }

    // Last block computes feature weights (threadfence + atomic pattern).
    if (threadIdx.x == 0) {
        __threadfence();
        const int old = atomicAdd(&d_cnt, 1);
        if (old == 63) {
            __threadfence();
            float s0 = 0.f, s1 = 0.f;
            for (int i = 0; i < B; ++i) { s0 += score[i]; s1 += score[B + i]; }
            const float inv = 1.f / (s0 + s1);
            out[OFF_FW + 0] = s0 * inv;
            out[OFF_FW + 1] = s1 * inv;
            d_cnt = 0;   // reset for graph replay determinism
        }
    }
}

// ---------------------------------------------------------------------------
extern "C" void kernel_launch(void* const* d_in, const int* in_sizes, int n_in,
                              void* d_out, int out_size) {
    const float* Tf0 = (const float*)d_in[0];
    const float* Tf1 = (const float*)d_in[1];
    const float* Sf0 = (const float*)d_in[2];
    const float* Sf1 = (const float*)d_in[3];
    const float* g0  = (const float*)d_in[4];
    const float* g1  = (const float*)d_in[5];
    float* out = (float*)d_out;

    float *w0, *w1, *pc0, *pt0, *ps0, *pc1, *pt1, *ps1, *score;
    cudaGetSymbolAddress((void**)&w0,  d_w0);
    cudaGetSymbolAddress((void**)&w1,  d_w1);
    cudaGetSymbolAddress((void**)&pc0, d_pc0);
    cudaGetSymbolAddress((void**)&pt0, d_pt0);
    cudaGetSymbolAddress((void**)&ps0, d_ps0);
    cudaGetSymbolAddress((void**)&pc1, d_pc1);
    cudaGetSymbolAddress((void**)&pt1, d_pt1);
    cudaGetSymbolAddress((void**)&ps1, d_ps1);
    cudaGetSymbolAddress((void**)&score, d_score);

    // Stage 1: GradCAM weights (all-float4)
    k_gmean_all<<<2048, 256>>>(g0, g1, w0, w1);

    // Stage 2: chunked partial cam / channel sums (proven R5/R6 kernel)
    {
        dim3 grid(3, B, NCH0 + NCH1);   // 3 x 32 x 24 = 2304 blocks of 128
        k_cam_all<<<grid, 128>>>(Tf0, Sf0, w0, pc0, pt0, ps0,
                                 Tf1, Sf1, w1, pc1, pt1, ps1);
    }

    // Stage 3: combine + stats + mask + fw (proven R6 kernel)
    k_finish_all<<<64, 512>>>(pc0, pt0, ps0, pc1, pt1, ps1, out, score);
}

// round 9
// speedup vs baseline: 1.1086x; 1.0504x over previous
#include <cuda_runtime.h>
#include <math_constants.h>

// Fixed shapes
#define B      32
#define C0     512
#define C1     1024
#define HW0    1444      // 38*38, divisible by 4
#define HW4_0  361       // HW0/4 in float4 units
#define HW1    361       // 19*19
#define THRESH 0.15f
#define NCH0   8         // channel chunks, level 0 (CPC = 64)
#define NCH1   16        // channel chunks, level 1 (CPC = 64)
#define CPC0   (C0/NCH0) // 64
#define CPC1   (C1/NCH1) // 64

// Output layout (float32): fw[2], embT0, embT1, embS0, embS1
#define OFF_FW  0
#define OFF_ET0 2
#define OFF_ET1 (OFF_ET0 + B*HW0)
#define OFF_ES0 (OFF_ET1 + B*HW1)
#define OFF_ES1 (OFF_ES0 + B*HW0)

// Static device scratch
__device__ float d_w0[B * C0];
__device__ float d_w1[B * C1];
__device__ float d_pc0[NCH0 * B * HW0];
__device__ float d_pt0[NCH0 * B * HW0];
__device__ float d_ps0[NCH0 * B * HW0];
__device__ float d_pc1[NCH1 * B * HW1];
__device__ float d_pt1[NCH1 * B * HW1];
__device__ float d_ps1[NCH1 * B * HW1];
__device__ float d_score[2 * B];
__device__ int   d_cnt = 0;

// ---------------------------------------------------------------------------
// Stage 1 (R4/R6 structure, deeper unroll): one warp owns rows of a single
// level. Blocks [0,1024): level-0 row-pairs (float4). Blocks [1024,2048):
// level-1 row-quads (scalar, interleaved).
// ---------------------------------------------------------------------------
__global__ __launch_bounds__(256)
void k_gmean_all(const float* __restrict__ g0, const float* __restrict__ g1,
                 float* __restrict__ w0, float* __restrict__ w1) {
    const int lane = threadIdx.x & 31;
    const int warp = threadIdx.x >> 5;

    if (blockIdx.x < 1024) {
        // level 0: 8192 row-pairs total
        const int pair = blockIdx.x * 8 + warp;
        const float4* p0 = reinterpret_cast<const float4*>(g0) + (size_t)(2 * pair) * HW4_0;
        const float4* p1 = p0 + HW4_0;
        float4 a0 = {0,0,0,0}, a1 = {0,0,0,0};
        #pragma unroll 4
        for (int i = lane; i < HW4_0; i += 32) {
            float4 v0 = __ldcs(p0 + i);
            float4 v1 = __ldcs(p1 + i);
            a0.x += v0.x; a0.y += v0.y; a0.z += v0.z; a0.w += v0.w;
            a1.x += v1.x; a1.y += v1.y; a1.z += v1.z; a1.w += v1.w;
        }
        float s0 = (a0.x + a0.y) + (a0.z + a0.w);
        float s1 = (a1.x + a1.y) + (a1.z + a1.w);
        #pragma unroll
        for (int o = 16; o; o >>= 1) {
            s0 += __shfl_xor_sync(0xffffffffu, s0, o);
            s1 += __shfl_xor_sync(0xffffffffu, s1, o);
        }
        if (lane == 0) {
            w0[2 * pair]     = s0 * (1.f / HW0);
            w0[2 * pair + 1] = s1 * (1.f / HW0);
        }
    } else {
        // level 1: 8192 row-quads total
        const int quad = (blockIdx.x - 1024) * 8 + warp;
        const float* p = g1 + (size_t)(4 * quad) * HW1;
        float s0 = 0.f, s1 = 0.f, s2 = 0.f, s3 = 0.f;
        #pragma unroll 4
        for (int i = lane; i < HW1; i += 32) {
            s0 += __ldcs(p + i);
            s1 += __ldcs(p + HW1 + i);
            s2 += __ldcs(p + 2 * HW1 + i);
            s3 += __ldcs(p + 3 * HW1 + i);
        }
        #pragma unroll
        for (int o = 16; o; o >>= 1) {
            s0 += __shfl_xor_sync(0xffffffffu, s0, o);
            s1 += __shfl_xor_sync(0xffffffffu, s1, o);
            s2 += __shfl_xor_sync(0xffffffffu, s2, o);
            s3 += __shfl_xor_sync(0xffffffffu, s3, o);
        }
        if (lane == 0) {
            const float inv = 1.f / HW1;
            w1[4 * quad]     = s0 * inv;
            w1[4 * quad + 1] = s1 * inv;
            w1[4 * quad + 2] = s2 * inv;
            w1[4 * quad + 3] = s3 * inv;
        }
    }
}

// ---------------------------------------------------------------------------
// Stage 2 (R5/R6 proven version, unchanged): per channel-chunk partials.
// 128-thread blocks; grid = (3, B, NCH0+NCH1) = 2304 blocks.
// ---------------------------------------------------------------------------
__global__ __launch_bounds__(128)
void k_cam_all(const float* __restrict__ Tf0, const float* __restrict__ Sf0,
               const float* __restrict__ w0,
               float* __restrict__ pc0, float* __restrict__ pt0, float* __restrict__ ps0,
               const float* __restrict__ Tf1, const float* __restrict__ Sf1,
               const float* __restrict__ w1,
               float* __restrict__ pc1, float* __restrict__ pt1, float* __restrict__ ps1) {
    __shared__ float sw[64];

    const int b   = blockIdx.y;
    const int z   = blockIdx.z;
    const int tid = threadIdx.x;

    if (z < NCH0) {
        // ----- level 0: float4 along hw -----
        const int chunk = z;
        if (tid < CPC0) sw[tid] = w0[b * C0 + chunk * CPC0 + tid];
        __syncthreads();

        const int q = blockIdx.x * 128 + tid;   // float4 index within row
        if (q >= HW4_0) return;
        const size_t rb = (size_t)(b * C0 + chunk * CPC0) * HW4_0 + q;
        const float4* tp = reinterpret_cast<const float4*>(Tf0) + rb;
        const float4* sp = reinterpret_cast<const float4*>(Sf0) + rb;

        float4 ac = {0,0,0,0}, at = {0,0,0,0}, as4 = {0,0,0,0};
        #pragma unroll 8
        for (int c = 0; c < CPC0; ++c) {
            float4 t = __ldcs(tp + (size_t)c * HW4_0);
            float4 s = __ldcs(sp + (size_t)c * HW4_0);
            float  wv = sw[c];
            ac.x = fmaf(wv, t.x, ac.x); ac.y = fmaf(wv, t.y, ac.y);
            ac.z = fmaf(wv, t.z, ac.z); ac.w = fmaf(wv, t.w, ac.w);
            at.x += t.x; at.y += t.y; at.z += t.z; at.w += t.w;
            as4.x += s.x; as4.y += s.y; as4.z += s.z; as4.w += s.w;
        }
        const size_t o = (size_t)(chunk * B + b) * HW4_0 + q;
        reinterpret_cast<float4*>(pc0)[o] = ac;
        reinterpret_cast<float4*>(pt0)[o] = at;
        reinterpret_cast<float4*>(ps0)[o] = as4;
    } else {
        // ----- level 1: scalar along hw -----
        const int chunk = z - NCH0;
        if (tid < CPC1) sw[tid] = w1[b * C1 + chunk * CPC1 + tid];
        __syncthreads();

        const int hw = blockIdx.x * 128 + tid;
        if (hw >= HW1) return;
        const size_t rb = (size_t)(b * C1 + chunk * CPC1) * HW1 + hw;
        const float* tp = Tf1 + rb;
        const float* sp = Sf1 + rb;

        float ac = 0.f, at = 0.f, as_ = 0.f;
        #pragma unroll 8
        for (int c = 0; c < CPC1; ++c) {
            float t = __ldcs(tp + (size_t)c * HW1);
            float s = __ldcs(sp + (size_t)c * HW1);
            ac = fmaf(sw[c], t, ac);
            at += t;
            as_ += s;
        }
        const size_t o = (size_t)(chunk * B + b) * HW1 + hw;
        pc1[o] = ac; pt1[o] = at; ps1[o] = as_;
    }
}

// ---------------------------------------------------------------------------
// Stage 3: combine chunks + stats + mask + fw. 64 blocks x 1024 threads.
// ---------------------------------------------------------------------------
template <int C, int HW, int CHUNKS, int PPT>
__device__ __forceinline__
void finish_impl(const float* __restrict__ pc, const float* __restrict__ pt,
                 const float* __restrict__ ps,
                 float* __restrict__ outT, float* __restrict__ outS,
                 float* __restrict__ score_slot, int b,
                 float* smx, float* ssm, float* sthr) {
    constexpr float invC  = 1.f / (float)C;
    constexpr float invHW = 1.f / (float)HW;
    const int t = threadIdx.x;

    float camv[PPT], tv[PPT], sv[PPT];
    float mx = -CUDART_INF_F, sm = 0.f;

    #pragma unroll
    for (int p = 0; p < PPT; ++p) {
        const int i = p * 1024 + t;
        camv[p] = 0.f; tv[p] = 0.f; sv[p] = 0.f;
        if (i < HW) {
            float cc = 0.f, tt = 0.f, ss = 0.f;
            #pragma unroll
            for (int ch = 0; ch < CHUNKS; ++ch) {
                const size_t o = (size_t)(ch * B + b) * HW + i;
                cc += pc[o]; tt += pt[o]; ss += ps[o];
            }
            camv[p] = cc;
            tv[p]   = tt * invC;
            sv[p]   = ss * invC;
            mx = fmaxf(mx, cc);
            sm += fmaxf(cc, 0.f);
        }
    }

    smx[t] = mx; ssm[t] = sm;
    __syncthreads();
    #pragma unroll
    for (int s = 512; s; s >>= 1) {
        if (t < s) { smx[t] = fmaxf(smx[t], smx[t + s]); ssm[t] += ssm[t + s]; }
        __syncthreads();
    }
    if (t == 0) {
        *score_slot = ssm[0] * invHW;
        *sthr = fabsf(smx[0] * THRESH);
    }
    __syncthreads();
    const float thr = *sthr;

    #pragma unroll
    for (int p = 0; p < PPT; ++p) {
        const int i = p * 1024 + t;
        if (i < HW) {
            const bool m = camv[p] > thr;
            const size_t o = (size_t)b * HW + i;
            outT[o] = m ? tv[p] : 0.f;
            outS[o] = m ? sv[p] : 0.f;
        }
    }
}

__global__ __launch_bounds__(1024)
void k_finish_all(const float* __restrict__ pc0, const float* __restrict__ pt0,
                  const float* __restrict__ ps0,
                  const float* __restrict__ pc1, const float* __restrict__ pt1,
                  const float* __restrict__ ps1,
                  float* __restrict__ out, float* __restrict__ score) {
    __shared__ float smx[1024], ssm[1024];
    __shared__ float sthr;

    if (blockIdx.x < 32) {
        const int b = blockIdx.x;
        finish_impl<C0, HW0, NCH0, 2>(pc0, pt0, ps0,
                                      out + OFF_ET0, out + OFF_ES0,
                                      score + b, b, smx, ssm, &sthr);
    } else {
        const int b = blockIdx.x - 32;
        finish_impl<C1, HW1, NCH1, 1>(pc1, pt1, ps1,
                                      out + OFF_ET1, out + OFF_ES1,
                                      score + B + b, b, smx, ssm, &sthr);
    }

    // Last block computes feature weights (threadfence + atomic pattern).
    if (threadIdx.x == 0) {
        __threadfence();
        const int old = atomicAdd(&d_cnt, 1);
        if (old == 63) {
            __threadfence();
            float s0 = 0.f, s1 = 0.f;
            for (int i = 0; i < B; ++i) { s0 += score[i]; s1 += score[B + i]; }
            const float inv = 1.f / (s0 + s1);
            out[OFF_FW + 0] = s0 * inv;
            out[OFF_FW + 1] = s1 * inv;
            d_cnt = 0;   // reset for graph replay determinism
        }
    }
}

// ---------------------------------------------------------------------------
extern "C" void kernel_launch(void* const* d_in, const int* in_sizes, int n_in,
                              void* d_out, int out_size) {
    const float* Tf0 = (const float*)d_in[0];
    const float* Tf1 = (const float*)d_in[1];
    const float* Sf0 = (const float*)d_in[2];
    const float* Sf1 = (const float*)d_in[3];
    const float* g0  = (const float*)d_in[4];
    const float* g1  = (const float*)d_in[5];
    float* out = (float*)d_out;

    float *w0, *w1, *pc0, *pt0, *ps0, *pc1, *pt1, *ps1, *score;
    cudaGetSymbolAddress((void**)&w0,  d_w0);
    cudaGetSymbolAddress((void**)&w1,  d_w1);
    cudaGetSymbolAddress((void**)&pc0, d_pc0);
    cudaGetSymbolAddress((void**)&pt0, d_pt0);
    cudaGetSymbolAddress((void**)&ps0, d_ps0);
    cudaGetSymbolAddress((void**)&pc1, d_pc1);
    cudaGetSymbolAddress((void**)&pt1, d_pt1);
    cudaGetSymbolAddress((void**)&ps1, d_ps1);
    cudaGetSymbolAddress((void**)&score, d_score);

    // Stage 1: GradCAM weights (R6 structure, unroll 4)
    k_gmean_all<<<2048, 256>>>(g0, g1, w0, w1);

    // Stage 2: chunked partial cam / channel sums (proven R5/R6 kernel)
    {
        dim3 grid(3, B, NCH0 + NCH1);   // 3 x 32 x 24 = 2304 blocks of 128
        k_cam_all<<<grid, 128>>>(Tf0, Sf0, w0, pc0, pt0, ps0,
                                 Tf1, Sf1, w1, pc1, pt1, ps1);
    }

    // Stage 3: combine + stats + mask + fw (1024 threads/block)
    k_finish_all<<<64, 1024>>>(pc0, pt0, ps0, pc1, pt1, ps1, out, score);
}